// round 9
// baseline (speedup 1.0000x reference)
#include <cuda_runtime.h>
#include <cstdint>

#define B_     64
#define N_     256
#define INDIM  512
#define OUTDIM 512
#define KSLOT  8
#define DKDIM  64

// Scratch: H^T [b][feature][m] and W^T [out][in]
__device__ float g_ht[(size_t)B_ * OUTDIM * N_];
__device__ float g_wt[OUTDIM * INDIM];

// ---------------------------------------------------------------------------
__device__ __forceinline__ uint32_t tf32u(float x) {
    uint32_t r; asm("cvt.rna.tf32.f32 %0, %1;" : "=r"(r) : "f"(x)); return r;
}

__device__ __forceinline__ void mma_tf32(float c[4], const uint32_t a[4], const uint32_t b[2]) {
    asm volatile(
        "mma.sync.aligned.m16n8k8.row.col.f32.tf32.tf32.f32 "
        "{%0,%1,%2,%3}, {%4,%5,%6,%7}, {%8,%9}, {%0,%1,%2,%3};"
        : "+f"(c[0]), "+f"(c[1]), "+f"(c[2]), "+f"(c[3])
        : "r"(a[0]), "r"(a[1]), "r"(a[2]), "r"(a[3]), "r"(b[0]), "r"(b[1]));
}

__device__ __forceinline__ uint32_t smem_u32(const void* p) {
    uint32_t a;
    asm("{ .reg .u64 t; cvta.to.shared.u64 t, %1; cvt.u32.u64 %0, t; }" : "=r"(a) : "l"(p));
    return a;
}

#define CP16(dst_u32, src_ptr) \
    asm volatile("cp.async.cg.shared.global [%0], [%1], 16;" :: "r"(dst_u32), "l"(src_ptr))
#define CP_COMMIT() asm volatile("cp.async.commit_group;" ::: "memory")
#define CP_WAIT0()  asm volatile("cp.async.wait_group 0;" ::: "memory")

// Plain k-major smem: row pitch 36 floats (144 B).
// Fragment LDS.32 bank = (4*gid + tig + const) mod 32 -> perfect permutation,
// 1-phase conflict-free (per-lane, independent of tile counts).
#define PITCH 36

// ---------------------------------------------------------------------------
// Kernel 0: W^T  (Wt[n][k] = W[k][n])
// ---------------------------------------------------------------------------
__global__ __launch_bounds__(256) void wt_kernel(const float* __restrict__ W,
                                                 float* __restrict__ Wt) {
    __shared__ float t[32][33];
    const int bx = blockIdx.x * 32;   // out (n)
    const int by = blockIdx.y * 32;   // in  (k)
    #pragma unroll
    for (int i = 0; i < 4; i++)
        t[threadIdx.y + i * 8][threadIdx.x] = W[(size_t)(by + threadIdx.y + i * 8) * OUTDIM + bx + threadIdx.x];
    __syncthreads();
    #pragma unroll
    for (int i = 0; i < 4; i++)
        Wt[(size_t)(bx + threadIdx.y + i * 8) * INDIM + by + threadIdx.x] = t[threadIdx.x][threadIdx.y + i * 8];
}

// ---------------------------------------------------------------------------
// Fragment compute over one resident chunk buffer.
// AROWS = number of A rows in buffer (B rows follow at AROWS..).
// Warp tile = (MT*16) x (NT*8).
// ---------------------------------------------------------------------------
template <int MT, int NT, int AROWS>
__device__ __forceinline__ void chunk_mma(
    const float* __restrict__ Sf, float c[MT][NT][4],
    int rowA0, int rowB0, int gid, int tig)
{
    #pragma unroll
    for (int ks = 0; ks < 4; ks++) {
        const int kc = ks * 8 + tig;
        uint32_t bfr[NT][2];
        #pragma unroll
        for (int nt = 0; nt < NT; nt++) {
            const int row = AROWS + rowB0 + nt * 8 + gid;
            bfr[nt][0] = tf32u(Sf[row * PITCH + kc]);
            bfr[nt][1] = tf32u(Sf[row * PITCH + kc + 4]);
        }
        uint32_t afr[MT][4];
        #pragma unroll
        for (int mt = 0; mt < MT; mt++) {
            const int r0 = rowA0 + mt * 16 + gid;
            afr[mt][0] = tf32u(Sf[r0 * PITCH + kc]);
            afr[mt][1] = tf32u(Sf[(r0 + 8) * PITCH + kc]);
            afr[mt][2] = tf32u(Sf[r0 * PITCH + kc + 4]);
            afr[mt][3] = tf32u(Sf[(r0 + 8) * PITCH + kc + 4]);
        }
        #pragma unroll
        for (int mt = 0; mt < MT; mt++)
            #pragma unroll
            for (int nt = 0; nt < NT; nt++)
                mma_tf32(c[mt][nt], afr[mt], bfr[nt]);
    }
}

// ---------------------------------------------------------------------------
// Stage 1: HT[b][f][m] = relu( X @ W + bias )
// CTA 128(m) x 128(f), 4 warps (2x2) of 64x64. 16 k-chunks. Grid (4, 128).
// Buffer: A rows 0..127 (m), B rows 128..255 (f). 36 KB/buffer, dbl-buffered.
// ---------------------------------------------------------------------------
#define S1_BUFROWS 256
#define S1_BUFSZ   (S1_BUFROWS * PITCH)
#define S1_DYN     (2 * S1_BUFSZ * 4)
__global__ __launch_bounds__(128) void s1_linear_mma(
    const float* __restrict__ X, const float* __restrict__ Wt,
    const float* __restrict__ bias, float* __restrict__ HT)
{
    extern __shared__ float smf[];
    const uint32_t sb = smem_u32(smf);

    const int tid = threadIdx.x;
    const int warpId = tid >> 5, lid = tid & 31;
    const int gid = lid >> 2, tig = lid & 3;
    const int wr = warpId & 1;            // m: 2 warps * 64
    const int wc = warpId >> 1;           // f: 2 warps * 64
    const int mBase = blockIdx.y * 128;
    const int fBase = blockIdx.x * 128;

    auto issue = [&](int k0, int buf) {
        const uint32_t base = sb + buf * (S1_BUFSZ * 4);
        #pragma unroll
        for (int it = 0; it < 8; it++) {          // A(X): 128 rows x 8 quads
            int idx = tid + it * 128;
            int r = idx >> 3, c4 = idx & 7;
            CP16(base + (uint32_t)(r * PITCH + c4 * 4) * 4,
                 X + (size_t)(mBase + r) * INDIM + k0 + c4 * 4);
        }
        #pragma unroll
        for (int it = 0; it < 8; it++) {          // B(Wt): 128 rows x 8 quads
            int idx = tid + it * 128;
            int r = idx >> 3, c4 = idx & 7;
            CP16(base + (uint32_t)((128 + r) * PITCH + c4 * 4) * 4,
                 Wt + (size_t)(fBase + r) * INDIM + k0 + c4 * 4);
        }
        CP_COMMIT();
    };

    float c[4][8][4];
    #pragma unroll
    for (int mt = 0; mt < 4; mt++)
        #pragma unroll
        for (int nt = 0; nt < 8; nt++)
            #pragma unroll
            for (int i = 0; i < 4; i++) c[mt][nt][i] = 0.0f;

    issue(0, 0);
    const int NCHUNK = INDIM / 32;                // 16
    for (int cc = 0; cc < NCHUNK; cc++) {
        CP_WAIT0();
        __syncthreads();
        if (cc + 1 < NCHUNK) issue((cc + 1) * 32, (cc + 1) & 1);
        chunk_mma<4, 8, 128>(smf + (cc & 1) * S1_BUFSZ, c, wr * 64, wc * 64, gid, tig);
    }

    // Epilogue: bias + relu, write transposed HT[b][f][m]
    const int batch = mBase >> 8;                 // 128-tile never straddles batch
    float* dst = HT + (size_t)batch * OUTDIM * N_;
    const int mloc = (mBase & 255) + wr * 64;
    #pragma unroll
    for (int mt = 0; mt < 4; mt++) {
        int m0 = mloc + mt * 16 + gid;
        #pragma unroll
        for (int nt = 0; nt < 8; nt++) {
            int f0 = fBase + wc * 64 + nt * 8 + tig * 2;
            float b0 = bias[f0], b1 = bias[f0 + 1];
            dst[(size_t)f0 * N_ + m0]           = fmaxf(c[mt][nt][0] + b0, 0.0f);
            dst[(size_t)(f0 + 1) * N_ + m0]     = fmaxf(c[mt][nt][1] + b1, 0.0f);
            dst[(size_t)f0 * N_ + m0 + 8]       = fmaxf(c[mt][nt][2] + b0, 0.0f);
            dst[(size_t)(f0 + 1) * N_ + m0 + 8] = fmaxf(c[mt][nt][3] + b1, 0.0f);
        }
    }
}

// ---------------------------------------------------------------------------
// Stage 2: out[b,n,k*64+d] = sum_m adj[b,k,n,m] * HT[b][k*64+d][m]
// CTA 256(n) x 64(d), 4 warps row-stacked, each 64x64. 8 m-chunks.
// Grid (8, 64). Buffer: A rows 0..255 (n), B rows 256..319 (d). 45 KB/buf.
// ---------------------------------------------------------------------------
#define S2_BUFROWS 320
#define S2_BUFSZ   (S2_BUFROWS * PITCH)
#define S2_DYN     (2 * S2_BUFSZ * 4)
__global__ __launch_bounds__(128) void s2_aggregate_mma(
    const float* __restrict__ adj, const float* __restrict__ HT,
    float* __restrict__ out)
{
    extern __shared__ float smf2[];
    const uint32_t sb = smem_u32(smf2);

    const int tid = threadIdx.x;
    const int warpId = tid >> 5, lid = tid & 31;
    const int gid = lid >> 2, tig = lid & 3;
    const int kslot = blockIdx.x;
    const int bIdx  = blockIdx.y;

    const float* A  = adj + (size_t)(bIdx * KSLOT + kslot) * N_ * N_;
    const float* Bp = HT + ((size_t)bIdx * OUTDIM + kslot * DKDIM) * N_;

    auto issue = [&](int m0, int buf) {
        const uint32_t base = sb + buf * (S2_BUFSZ * 4);
        #pragma unroll
        for (int it = 0; it < 16; it++) {         // A(adj): 256 rows x 8 quads
            int idx = tid + it * 128;
            int r = idx >> 3, c4 = idx & 7;
            CP16(base + (uint32_t)(r * PITCH + c4 * 4) * 4,
                 A + (size_t)r * N_ + m0 + c4 * 4);
        }
        #pragma unroll
        for (int it = 0; it < 4; it++) {          // B(HT): 64 rows x 8 quads
            int idx = tid + it * 128;
            int r = idx >> 3, c4 = idx & 7;
            CP16(base + (uint32_t)((256 + r) * PITCH + c4 * 4) * 4,
                 Bp + (size_t)r * N_ + m0 + c4 * 4);
        }
        CP_COMMIT();
    };

    float c[4][8][4];
    #pragma unroll
    for (int mt = 0; mt < 4; mt++)
        #pragma unroll
        for (int nt = 0; nt < 8; nt++)
            #pragma unroll
            for (int i = 0; i < 4; i++) c[mt][nt][i] = 0.0f;

    issue(0, 0);
    const int NCHUNK = N_ / 32;                   // 8
    for (int cc = 0; cc < NCHUNK; cc++) {
        CP_WAIT0();
        __syncthreads();
        if (cc + 1 < NCHUNK) issue((cc + 1) * 32, (cc + 1) & 1);
        chunk_mma<4, 8, 256>(smf2 + (cc & 1) * S2_BUFSZ, c, warpId * 64, 0, gid, tig);
    }

    // Epilogue: out[b][n][kslot*64 + d]
    float* dst = out + (size_t)bIdx * N_ * OUTDIM + kslot * DKDIM;
    #pragma unroll
    for (int mt = 0; mt < 4; mt++) {
        int n0 = warpId * 64 + mt * 16 + gid;
        #pragma unroll
        for (int nt = 0; nt < 8; nt++) {
            int d0 = nt * 8 + tig * 2;
            float2 v0 = make_float2(c[mt][nt][0], c[mt][nt][1]);
            float2 v1 = make_float2(c[mt][nt][2], c[mt][nt][3]);
            *reinterpret_cast<float2*>(dst + (size_t)n0 * OUTDIM + d0)       = v0;
            *reinterpret_cast<float2*>(dst + (size_t)(n0 + 8) * OUTDIM + d0) = v1;
        }
    }
}

// ---------------------------------------------------------------------------
extern "C" void kernel_launch(void* const* d_in, const int* in_sizes, int n_in,
                              void* d_out, int out_size)
{
    const float* node_feats = (const float*)d_in[0];  // (64,256,512)
    const float* adj        = (const float*)d_in[1];  // (64,8,256,256)
    const float* weight     = (const float*)d_in[2];  // (512,512)
    const float* bias       = (const float*)d_in[3];  // (512,)
    float* out = (float*)d_out;

    float *HT, *WT;
    cudaGetSymbolAddress((void**)&HT, g_ht);
    cudaGetSymbolAddress((void**)&WT, g_wt);

    cudaFuncSetAttribute(s1_linear_mma, cudaFuncAttributeMaxDynamicSharedMemorySize, S1_DYN);
    cudaFuncSetAttribute(s2_aggregate_mma, cudaFuncAttributeMaxDynamicSharedMemorySize, S2_DYN);

    wt_kernel<<<dim3(OUTDIM / 32, INDIM / 32), dim3(32, 8)>>>(weight, WT);
    s1_linear_mma<<<dim3(OUTDIM / 128, (B_ * N_) / 128), 128, S1_DYN>>>(node_feats, WT, bias, HT);
    s2_aggregate_mma<<<dim3(KSLOT, B_), 128, S2_DYN>>>(adj, HT, out);
}

// round 10
// speedup vs baseline: 1.1885x; 1.1885x over previous
#include <cuda_runtime.h>
#include <cuda_bf16.h>
#include <cstdint>

#define B_     64
#define N_     256
#define INDIM  512
#define OUTDIM 512
#define KSLOT  8
#define DKDIM  64

// Scratch: H^T [b][feature][m] and W^T [out][in]  (both fp32; cvt at staging)
__device__ float g_ht[(size_t)B_ * OUTDIM * N_];
__device__ float g_wt[OUTDIM * INDIM];

// ---------------------------------------------------------------------------
__device__ __forceinline__ uint32_t bf2(float x, float y) {
    __nv_bfloat162 t = __floats2bfloat162_rn(x, y);   // .x = low halfword
    return *reinterpret_cast<uint32_t*>(&t);
}

// D += A*B, m16n8k16, bf16 in, fp32 accum
__device__ __forceinline__ void mma_bf16(float c[4], const uint32_t a[4], const uint32_t b[2]) {
    asm volatile(
        "mma.sync.aligned.m16n8k16.row.col.f32.bf16.bf16.f32 "
        "{%0,%1,%2,%3}, {%4,%5,%6,%7}, {%8,%9}, {%0,%1,%2,%3};"
        : "+f"(c[0]), "+f"(c[1]), "+f"(c[2]), "+f"(c[3])
        : "r"(a[0]), "r"(a[1]), "r"(a[2]), "r"(a[3]), "r"(b[0]), "r"(b[1]));
}

// smem: rows of 32 k-elements as 16 uint32 (bf16x2 pairs), pitch 20 uint32.
// Fragment LDS.32 bank = (20*gid + tig + const) mod 32 -> perfect permutation.
#define PITCH 20
#define BUFROWS 192                       // A: rows 0..127, B: rows 128..191
#define BUFSZ  (BUFROWS * PITCH)          // uint32 per buffer

// ---------------------------------------------------------------------------
// Kernel 0: W^T  (Wt[n][k] = W[k][n]), fp32
// ---------------------------------------------------------------------------
__global__ __launch_bounds__(256) void wt_kernel(const float* __restrict__ W,
                                                 float* __restrict__ Wt) {
    __shared__ float t[32][33];
    const int bx = blockIdx.x * 32;   // out (n)
    const int by = blockIdx.y * 32;   // in  (k)
    #pragma unroll
    for (int i = 0; i < 4; i++)
        t[threadIdx.y + i * 8][threadIdx.x] = W[(size_t)(by + threadIdx.y + i * 8) * OUTDIM + bx + threadIdx.x];
    __syncthreads();
    #pragma unroll
    for (int i = 0; i < 4; i++)
        Wt[(size_t)(bx + threadIdx.y + i * 8) * INDIM + by + threadIdx.x] = t[threadIdx.x][threadIdx.y + i * 8];
}

// ---------------------------------------------------------------------------
// Fragment compute over one resident chunk (k=32 -> 2 k16 steps).
// Warp tile 64(m) x 32(n): MT=4, NT=4. B rows start at 128.
// ---------------------------------------------------------------------------
template <int MT, int NT>
__device__ __forceinline__ void chunk_mma(
    const uint32_t* __restrict__ S, float c[MT][NT][4],
    int rowA0, int rowB0, int gid, int tig)
{
    #pragma unroll
    for (int ks = 0; ks < 2; ks++) {
        const int kc = ks * 8 + tig;              // uint32 col of k-pair
        uint32_t bfr[NT][2];
        #pragma unroll
        for (int nt = 0; nt < NT; nt++) {
            const int row = 128 + rowB0 + nt * 8 + gid;
            bfr[nt][0] = S[row * PITCH + kc];
            bfr[nt][1] = S[row * PITCH + kc + 4];
        }
        uint32_t afr[MT][4];
        #pragma unroll
        for (int mt = 0; mt < MT; mt++) {
            const int r0 = rowA0 + mt * 16 + gid;
            afr[mt][0] = S[r0 * PITCH + kc];
            afr[mt][1] = S[(r0 + 8) * PITCH + kc];
            afr[mt][2] = S[r0 * PITCH + kc + 4];
            afr[mt][3] = S[(r0 + 8) * PITCH + kc + 4];
        }
        #pragma unroll
        for (int mt = 0; mt < MT; mt++)
            #pragma unroll
            for (int nt = 0; nt < NT; nt++)
                mma_bf16(c[mt][nt], afr[mt], bfr[nt]);
    }
}

// ---------------------------------------------------------------------------
// Stage 1: HT[b][f][m] = relu( X @ W + bias )
// CTA 128(m) x 64(f), 4 warps (2 wr x 2 wc), warp tile 64x32. 16 k-chunks.
// Grid (8, 128), 128 threads. LDG(fp32) -> cvt bf16 -> STS, double-buffered.
// ---------------------------------------------------------------------------
#define S_DYN (2 * BUFSZ * 4)
__global__ __launch_bounds__(128) void s1_linear_mma(
    const float* __restrict__ X, const float* __restrict__ Wt,
    const float* __restrict__ bias, float* __restrict__ HT)
{
    extern __shared__ uint32_t smu[];

    const int tid = threadIdx.x;
    const int warpId = tid >> 5, lid = tid & 31;
    const int gid = lid >> 2, tig = lid & 3;
    const int wr = warpId & 1;            // m: 2 warps * 64
    const int wc = warpId >> 1;           // f: 2 warps * 32
    const int mBase = blockIdx.y * 128;
    const int fBase = blockIdx.x * 64;

    float4 ar[8], br[4];

    auto loadA = [&](int k0) {            // X: 128 rows x 8 quads
        #pragma unroll
        for (int it = 0; it < 8; it++) {
            int idx = tid + it * 128;
            int r = idx >> 3, c4 = idx & 7;
            ar[it] = *reinterpret_cast<const float4*>(X + (size_t)(mBase + r) * INDIM + k0 + c4 * 4);
        }
    };
    auto loadB = [&](int k0) {            // Wt: 64 rows x 8 quads
        #pragma unroll
        for (int it = 0; it < 4; it++) {
            int idx = tid + it * 128;
            int r = idx >> 3, c4 = idx & 7;
            br[it] = *reinterpret_cast<const float4*>(Wt + (size_t)(fBase + r) * INDIM + k0 + c4 * 4);
        }
    };
    auto stsAll = [&](int buf) {
        uint32_t* base = smu + buf * BUFSZ;
        #pragma unroll
        for (int it = 0; it < 8; it++) {
            int idx = tid + it * 128;
            int r = idx >> 3, c4 = idx & 7;
            uint32_t* s = base + r * PITCH + c4 * 2;
            s[0] = bf2(ar[it].x, ar[it].y);
            s[1] = bf2(ar[it].z, ar[it].w);
        }
        #pragma unroll
        for (int it = 0; it < 4; it++) {
            int idx = tid + it * 128;
            int r = idx >> 3, c4 = idx & 7;
            uint32_t* s = base + (128 + r) * PITCH + c4 * 2;
            s[0] = bf2(br[it].x, br[it].y);
            s[1] = bf2(br[it].z, br[it].w);
        }
    };

    float c[4][4][4];
    #pragma unroll
    for (int mt = 0; mt < 4; mt++)
        #pragma unroll
        for (int nt = 0; nt < 4; nt++)
            #pragma unroll
            for (int i = 0; i < 4; i++) c[mt][nt][i] = 0.0f;

    loadA(0); loadB(0);
    stsAll(0);
    __syncthreads();

    const int NCHUNK = INDIM / 32;                // 16
    for (int cc = 0; cc < NCHUNK; cc++) {
        const bool hasNext = (cc + 1 < NCHUNK);
        if (hasNext) { loadA((cc + 1) * 32); loadB((cc + 1) * 32); }
        chunk_mma<4, 4>(smu + (cc & 1) * BUFSZ, c, wr * 64, wc * 32, gid, tig);
        if (hasNext) {
            stsAll((cc + 1) & 1);
            __syncthreads();
        }
    }

    // Epilogue: bias + relu, write transposed HT[b][f][m]
    const int batch = mBase >> 8;                 // 128-tile never straddles batch
    float* dst = HT + (size_t)batch * OUTDIM * N_;
    const int mloc = (mBase & 255) + wr * 64;
    #pragma unroll
    for (int mt = 0; mt < 4; mt++) {
        int m0 = mloc + mt * 16 + gid;
        #pragma unroll
        for (int nt = 0; nt < 4; nt++) {
            int f0 = fBase + wc * 32 + nt * 8 + tig * 2;
            float b0 = bias[f0], b1 = bias[f0 + 1];
            dst[(size_t)f0 * N_ + m0]           = fmaxf(c[mt][nt][0] + b0, 0.0f);
            dst[(size_t)(f0 + 1) * N_ + m0]     = fmaxf(c[mt][nt][1] + b1, 0.0f);
            dst[(size_t)f0 * N_ + m0 + 8]       = fmaxf(c[mt][nt][2] + b0, 0.0f);
            dst[(size_t)(f0 + 1) * N_ + m0 + 8] = fmaxf(c[mt][nt][3] + b1, 0.0f);
        }
    }
}

// ---------------------------------------------------------------------------
// Stage 2: out[b,n,k*64+d] = sum_m adj[b,k,n,m] * HT[b][k*64+d][m]
// CTA 128(n) x 64(d), 4 warps, warp tile 64x32. 8 m-chunks.
// Grid (2, 8, 64), 128 threads.
// ---------------------------------------------------------------------------
__global__ __launch_bounds__(128) void s2_aggregate_mma(
    const float* __restrict__ adj, const float* __restrict__ HT,
    float* __restrict__ out)
{
    extern __shared__ uint32_t smu2[];

    const int tid = threadIdx.x;
    const int warpId = tid >> 5, lid = tid & 31;
    const int gid = lid >> 2, tig = lid & 3;
    const int wr = warpId & 1;            // n: 2 warps * 64
    const int wc = warpId >> 1;           // d: 2 warps * 32
    const int nBase = blockIdx.x * 128;
    const int kslot = blockIdx.y;
    const int bIdx  = blockIdx.z;

    const float* A  = adj + (size_t)(bIdx * KSLOT + kslot) * N_ * N_;
    const float* Bp = HT + ((size_t)bIdx * OUTDIM + kslot * DKDIM) * N_;

    float4 ar[8], br[4];

    auto loadA = [&](int m0) {
        #pragma unroll
        for (int it = 0; it < 8; it++) {
            int idx = tid + it * 128;
            int r = idx >> 3, c4 = idx & 7;
            ar[it] = *reinterpret_cast<const float4*>(A + (size_t)(nBase + r) * N_ + m0 + c4 * 4);
        }
    };
    auto loadB = [&](int m0) {
        #pragma unroll
        for (int it = 0; it < 4; it++) {
            int idx = tid + it * 128;
            int r = idx >> 3, c4 = idx & 7;
            br[it] = *reinterpret_cast<const float4*>(Bp + (size_t)r * N_ + m0 + c4 * 4);
        }
    };
    auto stsAll = [&](int buf) {
        uint32_t* base = smu2 + buf * BUFSZ;
        #pragma unroll
        for (int it = 0; it < 8; it++) {
            int idx = tid + it * 128;
            int r = idx >> 3, c4 = idx & 7;
            uint32_t* s = base + r * PITCH + c4 * 2;
            s[0] = bf2(ar[it].x, ar[it].y);
            s[1] = bf2(ar[it].z, ar[it].w);
        }
        #pragma unroll
        for (int it = 0; it < 4; it++) {
            int idx = tid + it * 128;
            int r = idx >> 3, c4 = idx & 7;
            uint32_t* s = base + (128 + r) * PITCH + c4 * 2;
            s[0] = bf2(br[it].x, br[it].y);
            s[1] = bf2(br[it].z, br[it].w);
        }
    };

    float c[4][4][4];
    #pragma unroll
    for (int mt = 0; mt < 4; mt++)
        #pragma unroll
        for (int nt = 0; nt < 4; nt++)
            #pragma unroll
            for (int i = 0; i < 4; i++) c[mt][nt][i] = 0.0f;

    loadA(0); loadB(0);
    stsAll(0);
    __syncthreads();

    const int NCHUNK = N_ / 32;                   // 8
    for (int cc = 0; cc < NCHUNK; cc++) {
        const bool hasNext = (cc + 1 < NCHUNK);
        if (hasNext) { loadA((cc + 1) * 32); loadB((cc + 1) * 32); }
        chunk_mma<4, 4>(smu2 + (cc & 1) * BUFSZ, c, wr * 64, wc * 32, gid, tig);
        if (hasNext) {
            stsAll((cc + 1) & 1);
            __syncthreads();
        }
    }

    // Epilogue: out[b][n][kslot*64 + d]
    float* dst = out + (size_t)bIdx * N_ * OUTDIM + kslot * DKDIM;
    #pragma unroll
    for (int mt = 0; mt < 4; mt++) {
        int n0 = nBase + wr * 64 + mt * 16 + gid;
        #pragma unroll
        for (int nt = 0; nt < 4; nt++) {
            int d0 = wc * 32 + nt * 8 + tig * 2;
            float2 v0 = make_float2(c[mt][nt][0], c[mt][nt][1]);
            float2 v1 = make_float2(c[mt][nt][2], c[mt][nt][3]);
            *reinterpret_cast<float2*>(dst + (size_t)n0 * OUTDIM + d0)       = v0;
            *reinterpret_cast<float2*>(dst + (size_t)(n0 + 8) * OUTDIM + d0) = v1;
        }
    }
}

// ---------------------------------------------------------------------------
extern "C" void kernel_launch(void* const* d_in, const int* in_sizes, int n_in,
                              void* d_out, int out_size)
{
    const float* node_feats = (const float*)d_in[0];  // (64,256,512)
    const float* adj        = (const float*)d_in[1];  // (64,8,256,256)
    const float* weight     = (const float*)d_in[2];  // (512,512)
    const float* bias       = (const float*)d_in[3];  // (512,)
    float* out = (float*)d_out;

    float *HT, *WT;
    cudaGetSymbolAddress((void**)&HT, g_ht);
    cudaGetSymbolAddress((void**)&WT, g_wt);

    cudaFuncSetAttribute(s1_linear_mma, cudaFuncAttributeMaxDynamicSharedMemorySize, S_DYN);
    cudaFuncSetAttribute(s2_aggregate_mma, cudaFuncAttributeMaxDynamicSharedMemorySize, S_DYN);

    wt_kernel<<<dim3(OUTDIM / 32, INDIM / 32), dim3(32, 8)>>>(weight, WT);
    s1_linear_mma<<<dim3(OUTDIM / 64, (B_ * N_) / 128), 128, S_DYN>>>(node_feats, WT, bias, HT);
    s2_aggregate_mma<<<dim3(N_ / 128, KSLOT, B_), 128, S_DYN>>>(adj, HT, out);
}

// round 11
// speedup vs baseline: 1.2221x; 1.0284x over previous
#include <cuda_runtime.h>
#include <cuda_fp16.h>
#include <cstdint>

#define B_     64
#define N_     256
#define INDIM  512
#define OUTDIM 512
#define KSLOT  8
#define DKDIM  64

// Scratch: HT fp16 [b][feature][m], Wt fp16 [out][in]
__device__ __half g_ht_h[(size_t)B_ * OUTDIM * N_];
__device__ __half g_wt_h[OUTDIM * INDIM];

// ---------------------------------------------------------------------------
__device__ __forceinline__ uint32_t h2(float x, float y) {
    __half2 t = __floats2half2_rn(x, y);      // .x = low halfword
    return *reinterpret_cast<uint32_t*>(&t);
}

// D += A*B, m16n8k16, fp16 in, fp32 accum
__device__ __forceinline__ void mma_fp16(float c[4], const uint32_t a[4], const uint32_t b[2]) {
    asm volatile(
        "mma.sync.aligned.m16n8k16.row.col.f32.f16.f16.f32 "
        "{%0,%1,%2,%3}, {%4,%5,%6,%7}, {%8,%9}, {%0,%1,%2,%3};"
        : "+f"(c[0]), "+f"(c[1]), "+f"(c[2]), "+f"(c[3])
        : "r"(a[0]), "r"(a[1]), "r"(a[2]), "r"(a[3]), "r"(b[0]), "r"(b[1]));
}

__device__ __forceinline__ void ldm4(uint32_t& r0, uint32_t& r1, uint32_t& r2, uint32_t& r3,
                                     uint32_t addr) {
    asm volatile("ldmatrix.sync.aligned.m8n8.x4.shared.b16 {%0,%1,%2,%3}, [%4];"
                 : "=r"(r0), "=r"(r1), "=r"(r2), "=r"(r3) : "r"(addr));
}

__device__ __forceinline__ uint32_t smem_u32(const void* p) {
    uint32_t a;
    asm("{ .reg .u64 t; cvta.to.shared.u64 t, %1; cvt.u32.u64 %0, t; }" : "=r"(a) : "l"(p));
    return a;
}

#define CP16(dst_u32, src_ptr) \
    asm volatile("cp.async.cg.shared.global [%0], [%1], 16;" :: "r"(dst_u32), "l"(src_ptr))
#define CP_COMMIT() asm volatile("cp.async.commit_group;" ::: "memory")
#define CP_WAIT0()  asm volatile("cp.async.wait_group 0;" ::: "memory")

// Row = 32 fp16 k-elements = 16 uint32 + 4 pad -> PITCH 20 uint32 (80 B).
// ldmatrix phase reads 8 rows x 16B: start banks 20r mod 32 = perfect perm,
// each 16B spans 4 banks -> exactly all 32 banks per phase. Conflict-free.
#define PITCH 20
#define BUFROWS 192                       // A: rows 0..127, B: rows 128..191
#define BUFSZ  (BUFROWS * PITCH)          // uint32 per buffer
#define S_DYN  (2 * BUFSZ * 4)

// ---------------------------------------------------------------------------
// Kernel 0: Wt fp16  (Wt[n][k] = (half)W[k][n])
// ---------------------------------------------------------------------------
__global__ __launch_bounds__(256) void wt_kernel(const float* __restrict__ W,
                                                 __half* __restrict__ Wt) {
    __shared__ float t[32][33];
    const int bx = blockIdx.x * 32;   // out (n)
    const int by = blockIdx.y * 32;   // in  (k)
    #pragma unroll
    for (int i = 0; i < 4; i++)
        t[threadIdx.y + i * 8][threadIdx.x] = W[(size_t)(by + threadIdx.y + i * 8) * OUTDIM + bx + threadIdx.x];
    __syncthreads();
    #pragma unroll
    for (int i = 0; i < 4; i++)
        Wt[(size_t)(bx + threadIdx.y + i * 8) * INDIM + by + threadIdx.x] =
            __float2half_rn(t[threadIdx.x][threadIdx.y + i * 8]);
}

// ---------------------------------------------------------------------------
// Fragment compute over one resident chunk (k=32 -> 2 k16 steps), ldmatrix.
// Warp tile 64(m) x 32(n): MT=4, 2 B-pairs (4 nt). B rows start at 128.
// ---------------------------------------------------------------------------
__device__ __forceinline__ void chunk_mma_ldm(
    uint32_t sbase, float c[4][4][4], int rowA0, int rowB0, int lane)
{
    const int lr = lane & 15;                 // row within 16-row tile pair
    const int lc = lane >> 4;                 // k-seg half (0/1)
    #pragma unroll
    for (int ks = 0; ks < 2; ks++) {
        const uint32_t segoff = (uint32_t)(ks * 2 + lc) * 16u;   // bytes
        uint32_t afr[4][4];
        #pragma unroll
        for (int mt = 0; mt < 4; mt++) {
            uint32_t addr = sbase + (uint32_t)(rowA0 + mt * 16 + lr) * (PITCH * 4) + segoff;
            ldm4(afr[mt][0], afr[mt][1], afr[mt][2], afr[mt][3], addr);
        }
        uint32_t bfr[4][2];
        #pragma unroll
        for (int p = 0; p < 2; p++) {
            uint32_t addr = sbase + (uint32_t)(128 + rowB0 + p * 16 + lr) * (PITCH * 4) + segoff;
            uint32_t r0, r1, r2, r3;
            ldm4(r0, r1, r2, r3, addr);
            bfr[2 * p][0] = r0; bfr[2 * p + 1][0] = r1;
            bfr[2 * p][1] = r2; bfr[2 * p + 1][1] = r3;
        }
        #pragma unroll
        for (int mt = 0; mt < 4; mt++)
            #pragma unroll
            for (int nt = 0; nt < 4; nt++)
                mma_fp16(c[mt][nt], afr[mt], bfr[nt]);
    }
}

// ---------------------------------------------------------------------------
// Stage 1: HT[b][f][m] = (half) relu( X @ W + bias )
// CTA 128(m) x 64(f), 4 warps (2 wr x 2 wc), warp tile 64x32. 16 k-chunks.
// A(X fp32): LDG->cvt->STS ; B(Wt fp16): cp.async. Double-buffered.
// ---------------------------------------------------------------------------
__global__ __launch_bounds__(128) void s1_linear_mma(
    const float* __restrict__ X, const __half* __restrict__ Wt,
    const float* __restrict__ bias, __half* __restrict__ HT)
{
    extern __shared__ uint32_t smu[];
    const uint32_t sb = smem_u32(smu);

    const int tid = threadIdx.x;
    const int warpId = tid >> 5, lid = tid & 31;
    const int gid = lid >> 2, tig = lid & 3;
    const int wr = warpId & 1;            // m: 2 warps * 64
    const int wc = warpId >> 1;           // f: 2 warps * 32
    const int mBase = blockIdx.y * 128;
    const int fBase = blockIdx.x * 64;

    float4 ar[8];

    auto loadA = [&](int k0) {            // X: 128 rows x 8 quads
        #pragma unroll
        for (int it = 0; it < 8; it++) {
            int idx = tid + it * 128;
            int r = idx >> 3, c4 = idx & 7;
            ar[it] = *reinterpret_cast<const float4*>(X + (size_t)(mBase + r) * INDIM + k0 + c4 * 4);
        }
    };
    auto cpB = [&](int k0, int buf) {     // Wt fp16: 64 rows x 4 segs of 16B
        const uint32_t base = sb + buf * (BUFSZ * 4);
        #pragma unroll
        for (int it = 0; it < 2; it++) {
            int idx = tid + it * 128;
            int r = idx >> 2, s16 = idx & 3;
            CP16(base + (uint32_t)((128 + r) * PITCH + s16 * 4) * 4,
                 Wt + (size_t)(fBase + r) * INDIM + k0 + s16 * 8);
        }
        CP_COMMIT();
    };
    auto stsA = [&](int buf) {
        uint32_t* basep = smu + buf * BUFSZ;
        #pragma unroll
        for (int it = 0; it < 8; it++) {
            int idx = tid + it * 128;
            int r = idx >> 3, c4 = idx & 7;
            uint32_t* s = basep + r * PITCH + c4 * 2;
            s[0] = h2(ar[it].x, ar[it].y);
            s[1] = h2(ar[it].z, ar[it].w);
        }
    };

    float c[4][4][4];
    #pragma unroll
    for (int mt = 0; mt < 4; mt++)
        #pragma unroll
        for (int nt = 0; nt < 4; nt++)
            #pragma unroll
            for (int i = 0; i < 4; i++) c[mt][nt][i] = 0.0f;

    cpB(0, 0);
    loadA(0);
    stsA(0);
    CP_WAIT0();
    __syncthreads();

    const int NCHUNK = INDIM / 32;                // 16
    for (int cc = 0; cc < NCHUNK; cc++) {
        const bool hasNext = (cc + 1 < NCHUNK);
        if (hasNext) { loadA((cc + 1) * 32); cpB((cc + 1) * 32, (cc + 1) & 1); }
        chunk_mma_ldm(sb + (cc & 1) * (BUFSZ * 4), c, wr * 64, wc * 32, lid);
        if (hasNext) {
            stsA((cc + 1) & 1);
            CP_WAIT0();
            __syncthreads();
        }
    }

    // Epilogue: bias + relu, write transposed HT[b][f][m] as fp16
    const int batch = mBase >> 8;                 // 128-tile never straddles batch
    __half* dst = HT + (size_t)batch * OUTDIM * N_;
    const int mloc = (mBase & 255) + wr * 64;
    #pragma unroll
    for (int mt = 0; mt < 4; mt++) {
        int m0 = mloc + mt * 16 + gid;
        #pragma unroll
        for (int nt = 0; nt < 4; nt++) {
            int f0 = fBase + wc * 32 + nt * 8 + tig * 2;
            float b0 = bias[f0], b1 = bias[f0 + 1];
            dst[(size_t)f0 * N_ + m0]           = __float2half_rn(fmaxf(c[mt][nt][0] + b0, 0.0f));
            dst[(size_t)(f0 + 1) * N_ + m0]     = __float2half_rn(fmaxf(c[mt][nt][1] + b1, 0.0f));
            dst[(size_t)f0 * N_ + m0 + 8]       = __float2half_rn(fmaxf(c[mt][nt][2] + b0, 0.0f));
            dst[(size_t)(f0 + 1) * N_ + m0 + 8] = __float2half_rn(fmaxf(c[mt][nt][3] + b1, 0.0f));
        }
    }
}

// ---------------------------------------------------------------------------
// Stage 2: out[b,n,k*64+d] = sum_m adj[b,k,n,m] * HT[b][k*64+d][m]
// CTA 128(n) x 64(d), 4 warps, warp tile 64x32. 8 m-chunks.
// A(adj fp32): LDG->cvt->STS ; B(HT fp16): cp.async. Grid (2, 8, 64).
// ---------------------------------------------------------------------------
__global__ __launch_bounds__(128) void s2_aggregate_mma(
    const float* __restrict__ adj, const __half* __restrict__ HT,
    float* __restrict__ out)
{
    extern __shared__ uint32_t smu2[];
    const uint32_t sb = smem_u32(smu2);

    const int tid = threadIdx.x;
    const int warpId = tid >> 5, lid = tid & 31;
    const int gid = lid >> 2, tig = lid & 3;
    const int wr = warpId & 1;            // n: 2 warps * 64
    const int wc = warpId >> 1;           // d: 2 warps * 32
    const int nBase = blockIdx.x * 128;
    const int kslot = blockIdx.y;
    const int bIdx  = blockIdx.z;

    const float*  A  = adj + (size_t)(bIdx * KSLOT + kslot) * N_ * N_;
    const __half* Bp = HT + ((size_t)bIdx * OUTDIM + kslot * DKDIM) * N_;

    float4 ar[8];

    auto loadA = [&](int m0) {
        #pragma unroll
        for (int it = 0; it < 8; it++) {
            int idx = tid + it * 128;
            int r = idx >> 3, c4 = idx & 7;
            ar[it] = *reinterpret_cast<const float4*>(A + (size_t)(nBase + r) * N_ + m0 + c4 * 4);
        }
    };
    auto cpB = [&](int m0, int buf) {     // HT fp16: 64 rows x 4 segs of 16B
        const uint32_t base = sb + buf * (BUFSZ * 4);
        #pragma unroll
        for (int it = 0; it < 2; it++) {
            int idx = tid + it * 128;
            int r = idx >> 2, s16 = idx & 3;
            CP16(base + (uint32_t)((128 + r) * PITCH + s16 * 4) * 4,
                 Bp + (size_t)r * N_ + m0 + s16 * 8);
        }
        CP_COMMIT();
    };
    auto stsA = [&](int buf) {
        uint32_t* basep = smu2 + buf * BUFSZ;
        #pragma unroll
        for (int it = 0; it < 8; it++) {
            int idx = tid + it * 128;
            int r = idx >> 3, c4 = idx & 7;
            uint32_t* s = basep + r * PITCH + c4 * 2;
            s[0] = h2(ar[it].x, ar[it].y);
            s[1] = h2(ar[it].z, ar[it].w);
        }
    };

    float c[4][4][4];
    #pragma unroll
    for (int mt = 0; mt < 4; mt++)
        #pragma unroll
        for (int nt = 0; nt < 4; nt++)
            #pragma unroll
            for (int i = 0; i < 4; i++) c[mt][nt][i] = 0.0f;

    cpB(0, 0);
    loadA(0);
    stsA(0);
    CP_WAIT0();
    __syncthreads();

    const int NCHUNK = N_ / 32;                   // 8
    for (int cc = 0; cc < NCHUNK; cc++) {
        const bool hasNext = (cc + 1 < NCHUNK);
        if (hasNext) { loadA((cc + 1) * 32); cpB((cc + 1) * 32, (cc + 1) & 1); }
        chunk_mma_ldm(sb + (cc & 1) * (BUFSZ * 4), c, wr * 64, wc * 32, lid);
        if (hasNext) {
            stsA((cc + 1) & 1);
            CP_WAIT0();
            __syncthreads();
        }
    }

    // Epilogue: out[b][n][kslot*64 + d]  (fp32)
    float* dst = out + (size_t)bIdx * N_ * OUTDIM + kslot * DKDIM;
    #pragma unroll
    for (int mt = 0; mt < 4; mt++) {
        int n0 = nBase + wr * 64 + mt * 16 + gid;
        #pragma unroll
        for (int nt = 0; nt < 4; nt++) {
            int d0 = wc * 32 + nt * 8 + tig * 2;
            float2 v0 = make_float2(c[mt][nt][0], c[mt][nt][1]);
            float2 v1 = make_float2(c[mt][nt][2], c[mt][nt][3]);
            *reinterpret_cast<float2*>(dst + (size_t)n0 * OUTDIM + d0)       = v0;
            *reinterpret_cast<float2*>(dst + (size_t)(n0 + 8) * OUTDIM + d0) = v1;
        }
    }
}

// ---------------------------------------------------------------------------
extern "C" void kernel_launch(void* const* d_in, const int* in_sizes, int n_in,
                              void* d_out, int out_size)
{
    const float* node_feats = (const float*)d_in[0];  // (64,256,512)
    const float* adj        = (const float*)d_in[1];  // (64,8,256,256)
    const float* weight     = (const float*)d_in[2];  // (512,512)
    const float* bias       = (const float*)d_in[3];  // (512,)
    float* out = (float*)d_out;

    __half *HT, *WT;
    cudaGetSymbolAddress((void**)&HT, g_ht_h);
    cudaGetSymbolAddress((void**)&WT, g_wt_h);

    cudaFuncSetAttribute(s1_linear_mma, cudaFuncAttributeMaxDynamicSharedMemorySize, S_DYN);
    cudaFuncSetAttribute(s2_aggregate_mma, cudaFuncAttributeMaxDynamicSharedMemorySize, S_DYN);

    wt_kernel<<<dim3(OUTDIM / 32, INDIM / 32), dim3(32, 8)>>>(weight, WT);
    s1_linear_mma<<<dim3(OUTDIM / 64, (B_ * N_) / 128), 128, S_DYN>>>(node_feats, WT, bias, HT);
    s2_aggregate_mma<<<dim3(N_ / 128, KSLOT, B_), 128, S_DYN>>>(adj, HT, out);
}

// round 12
// speedup vs baseline: 1.3002x; 1.0639x over previous
#include <cuda_runtime.h>
#include <cuda_fp16.h>
#include <cstdint>

#define B_     64
#define N_     256
#define INDIM  512
#define OUTDIM 512
#define KSLOT  8
#define DKDIM  64

// Scratch: HT fp16 [b][feature][m], Wt fp16 [out][in]
__device__ __half g_ht_h[(size_t)B_ * OUTDIM * N_];
__device__ __half g_wt_h[OUTDIM * INDIM];

// ---------------------------------------------------------------------------
__device__ __forceinline__ uint32_t h2(float x, float y) {
    __half2 t = __floats2half2_rn(x, y);      // .x = low halfword
    return *reinterpret_cast<uint32_t*>(&t);
}

__device__ __forceinline__ void mma_fp16(float c[4], const uint32_t a[4], const uint32_t b[2]) {
    asm volatile(
        "mma.sync.aligned.m16n8k16.row.col.f32.f16.f16.f32 "
        "{%0,%1,%2,%3}, {%4,%5,%6,%7}, {%8,%9}, {%0,%1,%2,%3};"
        : "+f"(c[0]), "+f"(c[1]), "+f"(c[2]), "+f"(c[3])
        : "r"(a[0]), "r"(a[1]), "r"(a[2]), "r"(a[3]), "r"(b[0]), "r"(b[1]));
}

__device__ __forceinline__ void ldm4(uint32_t& r0, uint32_t& r1, uint32_t& r2, uint32_t& r3,
                                     uint32_t addr) {
    asm volatile("ldmatrix.sync.aligned.m8n8.x4.shared.b16 {%0,%1,%2,%3}, [%4];"
                 : "=r"(r0), "=r"(r1), "=r"(r2), "=r"(r3) : "r"(addr));
}

__device__ __forceinline__ uint32_t smem_u32(const void* p) {
    uint32_t a;
    asm("{ .reg .u64 t; cvta.to.shared.u64 t, %1; cvt.u32.u64 %0, t; }" : "=r"(a) : "l"(p));
    return a;
}

#define CP16(dst_u32, src_ptr) \
    asm volatile("cp.async.cg.shared.global [%0], [%1], 16;" :: "r"(dst_u32), "l"(src_ptr))
#define CP_COMMIT() asm volatile("cp.async.commit_group;" ::: "memory")
#define CP_WAIT2()  asm volatile("cp.async.wait_group 2;" ::: "memory")

// Row = 32 fp16 k-elements = 16 uint32 + 4 pad -> PITCH 20 uint32 (80 B).
// ldmatrix phase: 8 rows x 16B, start banks 20r mod 32 = perfect permutation.
#define PITCH   20
#define BUFROWS 192                       // A: rows 0..127, B: rows 128..191
#define BUFSZ   (BUFROWS * PITCH)         // uint32 per stage
#define NSTAGE  4
#define S_DYN   (NSTAGE * BUFSZ * 4)      // 61440 B

// ---------------------------------------------------------------------------
// Kernel 0: Wt fp16  (Wt[n][k] = (half)W[k][n])
// ---------------------------------------------------------------------------
__global__ __launch_bounds__(256) void wt_kernel(const float* __restrict__ W,
                                                 __half* __restrict__ Wt) {
    __shared__ float t[32][33];
    const int bx = blockIdx.x * 32;   // out (n)
    const int by = blockIdx.y * 32;   // in  (k)
    #pragma unroll
    for (int i = 0; i < 4; i++)
        t[threadIdx.y + i * 8][threadIdx.x] = W[(size_t)(by + threadIdx.y + i * 8) * OUTDIM + bx + threadIdx.x];
    __syncthreads();
    #pragma unroll
    for (int i = 0; i < 4; i++)
        Wt[(size_t)(bx + threadIdx.y + i * 8) * INDIM + by + threadIdx.x] =
            __float2half_rn(t[threadIdx.x][threadIdx.y + i * 8]);
}

// ---------------------------------------------------------------------------
// Fragment compute over one resident stage (k=32 -> 2 k16 steps), ldmatrix.
// Warp tile 64(m) x 32(n). B rows start at 128.
// ---------------------------------------------------------------------------
__device__ __forceinline__ void chunk_mma_ldm(
    uint32_t sbase, float c[4][4][4], int rowA0, int rowB0, int lane)
{
    const int lr = lane & 15;
    const int lc = lane >> 4;
    #pragma unroll
    for (int ks = 0; ks < 2; ks++) {
        const uint32_t segoff = (uint32_t)(ks * 2 + lc) * 16u;   // bytes
        uint32_t afr[4][4];
        #pragma unroll
        for (int mt = 0; mt < 4; mt++) {
            uint32_t addr = sbase + (uint32_t)(rowA0 + mt * 16 + lr) * (PITCH * 4) + segoff;
            ldm4(afr[mt][0], afr[mt][1], afr[mt][2], afr[mt][3], addr);
        }
        uint32_t bfr[4][2];
        #pragma unroll
        for (int p = 0; p < 2; p++) {
            uint32_t addr = sbase + (uint32_t)(128 + rowB0 + p * 16 + lr) * (PITCH * 4) + segoff;
            uint32_t r0, r1, r2, r3;
            ldm4(r0, r1, r2, r3, addr);
            bfr[2 * p][0] = r0; bfr[2 * p + 1][0] = r1;
            bfr[2 * p][1] = r2; bfr[2 * p + 1][1] = r3;
        }
        #pragma unroll
        for (int mt = 0; mt < 4; mt++)
            #pragma unroll
            for (int nt = 0; nt < 4; nt++)
                mma_fp16(c[mt][nt], afr[mt], bfr[nt]);
    }
}

// ---------------------------------------------------------------------------
// Stage 1: HT[b][f][m] = (half) relu( X @ W + bias )
// CTA 128(m) x 64(f), 4 warps, warp tile 64x32. 16 k-chunks, 4-stage pipe.
// A(X fp32): LDG -> (next iter) cvt+STS ; B(Wt fp16): cp.async.
// ---------------------------------------------------------------------------
__global__ __launch_bounds__(128) void s1_linear_mma(
    const float* __restrict__ X, const __half* __restrict__ Wt,
    const float* __restrict__ bias, __half* __restrict__ HT)
{
    extern __shared__ uint32_t smu[];
    const uint32_t sb = smem_u32(smu);

    const int tid = threadIdx.x;
    const int warpId = tid >> 5, lid = tid & 31;
    const int gid = lid >> 2, tig = lid & 3;
    const int wr = warpId & 1;            // m: 2 warps * 64
    const int wc = warpId >> 1;           // f: 2 warps * 32
    const int mBase = blockIdx.y * 128;
    const int fBase = blockIdx.x * 64;

    float4 ar[8];

    auto ldgA = [&](int k0) {             // X: 128 rows x 8 quads
        #pragma unroll
        for (int it = 0; it < 8; it++) {
            int idx = tid + it * 128;
            int r = idx >> 3, c4 = idx & 7;
            ar[it] = *reinterpret_cast<const float4*>(X + (size_t)(mBase + r) * INDIM + k0 + c4 * 4);
        }
    };
    auto stsA = [&](int st) {
        uint32_t* basep = smu + st * BUFSZ;
        #pragma unroll
        for (int it = 0; it < 8; it++) {
            int idx = tid + it * 128;
            int r = idx >> 3, c4 = idx & 7;
            uint32_t* s = basep + r * PITCH + c4 * 2;
            s[0] = h2(ar[it].x, ar[it].y);
            s[1] = h2(ar[it].z, ar[it].w);
        }
    };
    auto cpB = [&](int k0, int st) {      // Wt fp16: 64 rows x 4 segs of 16B
        const uint32_t base = sb + st * (BUFSZ * 4);
        #pragma unroll
        for (int it = 0; it < 2; it++) {
            int idx = tid + it * 128;
            int r = idx >> 2, s16 = idx & 3;
            CP16(base + (uint32_t)((128 + r) * PITCH + s16 * 4) * 4,
                 Wt + (size_t)(fBase + r) * INDIM + k0 + s16 * 8);
        }
        CP_COMMIT();
    };

    float c[4][4][4];
    #pragma unroll
    for (int mt = 0; mt < 4; mt++)
        #pragma unroll
        for (int nt = 0; nt < 4; nt++)
            #pragma unroll
            for (int i = 0; i < 4; i++) c[mt][nt][i] = 0.0f;

    // Prologue: stages 0..2 fully staged; chunk 3's A in regs.
    cpB(0, 0); cpB(32, 1); cpB(64, 2);
    ldgA(0);  stsA(0);
    ldgA(32); stsA(1);
    ldgA(64); stsA(2);
    ldgA(96);

    const int NCHUNK = INDIM / 32;                // 16
    for (int cc = 0; cc < NCHUNK; cc++) {
        CP_WAIT2();
        __syncthreads();
        const int j = cc + 3;
        if (j < NCHUNK) { stsA(j & 3); cpB(j * 32, j & 3); }
        if (cc + 4 < NCHUNK) ldgA((cc + 4) * 32);
        chunk_mma_ldm(sb + (cc & 3) * (BUFSZ * 4), c, wr * 64, wc * 32, lid);
    }

    // Epilogue: bias + relu, write transposed HT[b][f][m] as fp16
    const int batch = mBase >> 8;
    __half* dst = HT + (size_t)batch * OUTDIM * N_;
    const int mloc = (mBase & 255) + wr * 64;
    #pragma unroll
    for (int mt = 0; mt < 4; mt++) {
        int m0 = mloc + mt * 16 + gid;
        #pragma unroll
        for (int nt = 0; nt < 4; nt++) {
            int f0 = fBase + wc * 32 + nt * 8 + tig * 2;
            float b0 = bias[f0], b1 = bias[f0 + 1];
            dst[(size_t)f0 * N_ + m0]           = __float2half_rn(fmaxf(c[mt][nt][0] + b0, 0.0f));
            dst[(size_t)(f0 + 1) * N_ + m0]     = __float2half_rn(fmaxf(c[mt][nt][1] + b1, 0.0f));
            dst[(size_t)f0 * N_ + m0 + 8]       = __float2half_rn(fmaxf(c[mt][nt][2] + b0, 0.0f));
            dst[(size_t)(f0 + 1) * N_ + m0 + 8] = __float2half_rn(fmaxf(c[mt][nt][3] + b1, 0.0f));
        }
    }
}

// ---------------------------------------------------------------------------
// Stage 2: out[b,n,k*64+d] = sum_m adj[b,k,n,m] * HT[b][k*64+d][m]
// CTA 128(n) x 64(d), 4 warps, warp tile 64x32. 8 m-chunks, 4-stage pipe.
// A(adj fp32): LDG -> (next iter) cvt+STS ; B(HT fp16): cp.async.
// ---------------------------------------------------------------------------
__global__ __launch_bounds__(128) void s2_aggregate_mma(
    const float* __restrict__ adj, const __half* __restrict__ HT,
    float* __restrict__ out)
{
    extern __shared__ uint32_t smu2[];
    const uint32_t sb = smem_u32(smu2);

    const int tid = threadIdx.x;
    const int warpId = tid >> 5, lid = tid & 31;
    const int gid = lid >> 2, tig = lid & 3;
    const int wr = warpId & 1;            // n: 2 warps * 64
    const int wc = warpId >> 1;           // d: 2 warps * 32
    const int nBase = blockIdx.x * 128;
    const int kslot = blockIdx.y;
    const int bIdx  = blockIdx.z;

    const float*  A  = adj + (size_t)(bIdx * KSLOT + kslot) * N_ * N_;
    const __half* Bp = HT + ((size_t)bIdx * OUTDIM + kslot * DKDIM) * N_;

    float4 ar[8];

    auto ldgA = [&](int m0) {
        #pragma unroll
        for (int it = 0; it < 8; it++) {
            int idx = tid + it * 128;
            int r = idx >> 3, c4 = idx & 7;
            ar[it] = *reinterpret_cast<const float4*>(A + (size_t)(nBase + r) * N_ + m0 + c4 * 4);
        }
    };
    auto stsA = [&](int st) {
        uint32_t* basep = smu2 + st * BUFSZ;
        #pragma unroll
        for (int it = 0; it < 8; it++) {
            int idx = tid + it * 128;
            int r = idx >> 3, c4 = idx & 7;
            uint32_t* s = basep + r * PITCH + c4 * 2;
            s[0] = h2(ar[it].x, ar[it].y);
            s[1] = h2(ar[it].z, ar[it].w);
        }
    };
    auto cpB = [&](int m0, int st) {      // HT fp16: 64 rows x 4 segs of 16B
        const uint32_t base = sb + st * (BUFSZ * 4);
        #pragma unroll
        for (int it = 0; it < 2; it++) {
            int idx = tid + it * 128;
            int r = idx >> 2, s16 = idx & 3;
            CP16(base + (uint32_t)((128 + r) * PITCH + s16 * 4) * 4,
                 Bp + (size_t)r * N_ + m0 + s16 * 8);
        }
        CP_COMMIT();
    };

    float c[4][4][4];
    #pragma unroll
    for (int mt = 0; mt < 4; mt++)
        #pragma unroll
        for (int nt = 0; nt < 4; nt++)
            #pragma unroll
            for (int i = 0; i < 4; i++) c[mt][nt][i] = 0.0f;

    // Prologue
    cpB(0, 0); cpB(32, 1); cpB(64, 2);
    ldgA(0);  stsA(0);
    ldgA(32); stsA(1);
    ldgA(64); stsA(2);
    ldgA(96);

    const int NCHUNK = N_ / 32;                   // 8
    for (int cc = 0; cc < NCHUNK; cc++) {
        CP_WAIT2();
        __syncthreads();
        const int j = cc + 3;
        if (j < NCHUNK) { stsA(j & 3); cpB(j * 32, j & 3); }
        if (cc + 4 < NCHUNK) ldgA((cc + 4) * 32);
        chunk_mma_ldm(sb + (cc & 3) * (BUFSZ * 4), c, wr * 64, wc * 32, lid);
    }

    // Epilogue: out[b][n][kslot*64 + d]  (fp32)
    float* dst = out + (size_t)bIdx * N_ * OUTDIM + kslot * DKDIM;
    #pragma unroll
    for (int mt = 0; mt < 4; mt++) {
        int n0 = nBase + wr * 64 + mt * 16 + gid;
        #pragma unroll
        for (int nt = 0; nt < 4; nt++) {
            int d0 = wc * 32 + nt * 8 + tig * 2;
            float2 v0 = make_float2(c[mt][nt][0], c[mt][nt][1]);
            float2 v1 = make_float2(c[mt][nt][2], c[mt][nt][3]);
            *reinterpret_cast<float2*>(dst + (size_t)n0 * OUTDIM + d0)       = v0;
            *reinterpret_cast<float2*>(dst + (size_t)(n0 + 8) * OUTDIM + d0) = v1;
        }
    }
}

// ---------------------------------------------------------------------------
extern "C" void kernel_launch(void* const* d_in, const int* in_sizes, int n_in,
                              void* d_out, int out_size)
{
    const float* node_feats = (const float*)d_in[0];  // (64,256,512)
    const float* adj        = (const float*)d_in[1];  // (64,8,256,256)
    const float* weight     = (const float*)d_in[2];  // (512,512)
    const float* bias       = (const float*)d_in[3];  // (512,)
    float* out = (float*)d_out;

    __half *HT, *WT;
    cudaGetSymbolAddress((void**)&HT, g_ht_h);
    cudaGetSymbolAddress((void**)&WT, g_wt_h);

    cudaFuncSetAttribute(s1_linear_mma, cudaFuncAttributeMaxDynamicSharedMemorySize, S_DYN);
    cudaFuncSetAttribute(s2_aggregate_mma, cudaFuncAttributeMaxDynamicSharedMemorySize, S_DYN);

    wt_kernel<<<dim3(OUTDIM / 32, INDIM / 32), dim3(32, 8)>>>(weight, WT);
    s1_linear_mma<<<dim3(OUTDIM / 64, (B_ * N_) / 128), 128, S_DYN>>>(node_feats, WT, bias, HT);
    s2_aggregate_mma<<<dim3(N_ / 128, KSLOT, B_), 128, S_DYN>>>(adj, HT, out);
}